// round 9
// baseline (speedup 1.0000x reference)
#include <cuda_runtime.h>
#include <math.h>
#include <cstdint>

#define B_DIM   2048
#define HID     512
#define DIM_OUT 256
#define MAXN    128
#define MID_S   256
#define MID_K   320
#define MID_D   384

#define X_SIZE  (2048LL*128*256)
#define N_OFF   X_SIZE
#define MASK_OFF (X_SIZE + 2048LL)

__device__ __align__(16) float g_keys[MAXN * HID];
__device__ int   g_n[B_DIM];
// W1^T k16-interleaved: [32 chunks][384 n][16]  (pos p holds k = 4*(p%4)+p/4)
__device__ __align__(16) float g_W1c[32 * 384 * 16];
// W2^T k16-interleaved: [24 chunks][256 n][16]
__device__ __align__(16) float g_W2c[24 * 256 * 16];

__device__ __forceinline__ float mishf(float x) {
    float sp = fmaxf(x, 0.f) + log1pf(expf(-fabsf(x)));
    return x * tanhf(sp);
}
__device__ __forceinline__ float mish_fast(float x) {
    float e = __expf(x);
    float y = 1.f + e;
    float d = fmaf(y, y, 1.f);
    return x - 2.f * x * __frcp_rn(d);
}
__device__ __forceinline__ float tf32r(float x) {
    uint32_t u;
    asm("cvt.rna.tf32.f32 %0, %1;" : "=r"(u) : "f"(x));
    return __uint_as_float(u);
}
__device__ __forceinline__ void mma_tf32(float* c, const uint32_t* a,
                                         uint32_t b0, uint32_t b1) {
    asm volatile(
        "mma.sync.aligned.m16n8k8.row.col.f32.tf32.tf32.f32 "
        "{%0,%1,%2,%3}, {%4,%5,%6,%7}, {%8,%9}, {%0,%1,%2,%3};"
        : "+f"(c[0]), "+f"(c[1]), "+f"(c[2]), "+f"(c[3])
        : "r"(a[0]), "r"(a[1]), "r"(a[2]), "r"(a[3]), "r"(b0), "r"(b1));
}

// ===================== Kernel A: size_pred (4 rows/block) =====================
__global__ __launch_bounds__(256)
void sizepred_kernel(const float* __restrict__ z,
                     const float* __restrict__ W1, const float* __restrict__ b1,
                     const float* __restrict__ g,  const float* __restrict__ be,
                     const float* __restrict__ W2, const float* __restrict__ b2,
                     float* __restrict__ out, int write_n, int write_mask)
{
    __shared__ float zsh[4][HID];
    __shared__ float hsh[4][MID_S];
    __shared__ float smean[4], srstd[4];
    __shared__ int   nsh[4];
    const int b0  = blockIdx.x * 4;
    const int tid = threadIdx.x;

    #pragma unroll
    for (int e = 0; e < 8; ++e) {
        int lin = e * 256 + tid;
        int bb = lin >> 9, i = lin & 511;
        zsh[bb][i] = z[(size_t)(b0 + bb) * HID + i];
    }
    __syncthreads();

    const int j = tid;
    float acc[4];
    {
        float bj = b1[j];
        #pragma unroll
        for (int bb = 0; bb < 4; ++bb) acc[bb] = bj;
    }
    for (int i = 0; i < HID; i += 8) {
        #pragma unroll
        for (int ii = 0; ii < 8; ++ii) {
            float w = W1[(size_t)(i + ii) * MID_S + j];
            #pragma unroll
            for (int bb = 0; bb < 4; ++bb)
                acc[bb] = fmaf(zsh[bb][i + ii], w, acc[bb]);
        }
    }
    #pragma unroll
    for (int bb = 0; bb < 4; ++bb) hsh[bb][j] = acc[bb];
    __syncthreads();

    const int wrow = (tid >> 5) & 3, lane = tid & 31;
    {
        float s = 0.f, s2 = 0.f;
        for (int jj = lane; jj < MID_S; jj += 32) {
            float v = hsh[wrow][jj];
            s += v; s2 += v * v;
        }
        #pragma unroll
        for (int o = 16; o; o >>= 1) {
            s  += __shfl_xor_sync(0xffffffffu, s,  o);
            s2 += __shfl_xor_sync(0xffffffffu, s2, o);
        }
        if (lane == 0) {
            float m = s * (1.f / MID_S);
            float var = s2 * (1.f / MID_S) - m * m;
            smean[wrow] = m;
            srstd[wrow] = rsqrtf(var + 1e-5f);
        }
    }
    __syncthreads();

    {
        float gj = g[j], bej = be[j], w2j = W2[j];
        #pragma unroll
        for (int bb = 0; bb < 4; ++bb) {
            float v = (acc[bb] - smean[bb]) * srstd[bb] * gj + bej;
            hsh[bb][j] = mishf(v) * w2j;
        }
    }
    __syncthreads();

    {
        float s = 0.f;
        for (int jj = lane; jj < MID_S; jj += 32) s += hsh[wrow][jj];
        #pragma unroll
        for (int o = 16; o; o >>= 1) s += __shfl_xor_sync(0xffffffffu, s, o);
        if (lane == 0) {
            float logit = s + b2[0];
            float nf = fminf(fmaxf(rintf(logit), 0.f), (float)MAXN);
            int ni = (int)nf;
            g_n[b0 + wrow] = ni;
            nsh[wrow] = ni;
            if (write_n) out[N_OFF + b0 + wrow] = nf;
        }
    }
    __syncthreads();

    if (write_mask) {
        #pragma unroll
        for (int e = 0; e < 2; ++e) {
            int lin = e * 256 + tid;
            int bb = lin >> 7, kk = lin & 127;
            out[MASK_OFF + (size_t)(b0 + bb) * MAXN + kk] = (kk < nsh[bb]) ? 1.f : 0.f;
        }
    }
}

// ===================== Kernel B: keys =====================
__global__ __launch_bounds__(512)
void keys_kernel(const float* __restrict__ W1, const float* __restrict__ b1,
                 const float* __restrict__ g,  const float* __restrict__ be,
                 const float* __restrict__ W2, const float* __restrict__ b2)
{
    __shared__ float hs[MID_K];
    __shared__ float warp_s[16], warp_s2[16];
    __shared__ float st_mean, st_rstd;
    const int k = blockIdx.x;
    const int tid = threadIdx.x;
    const bool act = tid < MID_K;
    float v = 0.f;
    if (act) v = W1[(size_t)k * MID_K + tid] + b1[tid];
    float s = v, s2 = v * v;
    #pragma unroll
    for (int o = 16; o; o >>= 1) {
        s  += __shfl_xor_sync(0xffffffffu, s,  o);
        s2 += __shfl_xor_sync(0xffffffffu, s2, o);
    }
    const int wid = tid >> 5, lane = tid & 31;
    if (lane == 0) { warp_s[wid] = s; warp_s2[wid] = s2; }
    __syncthreads();
    if (wid == 0) {
        float ps  = (lane < 16) ? warp_s[lane]  : 0.f;
        float ps2 = (lane < 16) ? warp_s2[lane] : 0.f;
        #pragma unroll
        for (int o = 8; o; o >>= 1) {
            ps  += __shfl_xor_sync(0xffffffffu, ps,  o);
            ps2 += __shfl_xor_sync(0xffffffffu, ps2, o);
        }
        if (lane == 0) {
            float m = ps * (1.f / MID_K);
            float var = ps2 * (1.f / MID_K) - m * m;
            st_mean = m;
            st_rstd = rsqrtf(var + 1e-5f);
        }
    }
    __syncthreads();
    if (act) hs[tid] = mishf((v - st_mean) * st_rstd * g[tid] + be[tid]);
    __syncthreads();
    const int o = tid;
    float acc = b2[o];
    for (int jj = 0; jj < MID_K; jj += 4) {
        #pragma unroll
        for (int u = 0; u < 4; ++u)
            acc = fmaf(hs[jj + u], W2[(size_t)(jj + u) * HID + o], acc);
    }
    g_keys[(size_t)k * HID + o] = acc;
}

// ===================== Prep: k16-interleaved transposed tf32 weights =====================
#define W1C_TOTAL (32 * 384 * 16)   // 196608
#define W2C_TOTAL (24 * 256 * 16)   // 98304
__global__ __launch_bounds__(256)
void prep_kernel(const float* __restrict__ W1, const float* __restrict__ W2)
{
    int id = blockIdx.x * 256 + threadIdx.x;
    if (id < W1C_TOTAL) {
        int kt = id / 6144, rem = id % 6144;
        int nn = rem >> 4, p = rem & 15;
        int ko = 4 * (p & 3) + (p >> 2);
        g_W1c[id] = tf32r(W1[(size_t)(kt * 16 + ko) * MID_D + nn]);
    } else if (id < W1C_TOTAL + W2C_TOTAL) {
        int t = id - W1C_TOTAL;
        int kt = t / 4096, rem = t % 4096;
        int nn = rem >> 4, p = rem & 15;
        int ko = 4 * (p & 3) + (p >> 2);
        g_W2c[t] = tf32r(W2[(size_t)(kt * 16 + ko) * DIM_OUT + nn]);
    }
}

// ===================== Kernel C: interleaved-A tf32 decoder, 2 CTAs/SM =====================
// A smem: [32 kt][32 rows][16]  (pos p <-> k = 4*(p%4)+p/4), 16384 floats
// H smem: [24 kt][32 rows][16] aliased on A, 12288 floats
#define OFF_Z_FLOATS 16384
#define DEC_SMEM_BYTES ((OFF_Z_FLOATS + 512) * 4)  // 67584

__global__ __launch_bounds__(256, 2)
void decoder_kernel(const float* __restrict__ z,
                    const float* __restrict__ b1c,
                    const float* __restrict__ b2c,
                    float* __restrict__ out)
{
    extern __shared__ float sm[];
    float* As = sm;
    float* Hs = sm;
    float* zs = sm + OFF_Z_FLOATS;

    const int b    = blockIdx.x >> 2;
    const int r0   = (blockIdx.x & 3) * 32;
    const int tid  = threadIdx.x;
    const int wc   = tid >> 5;          // 0..7 warp col
    const int lane = tid & 31;
    const int tg   = lane >> 2;         // 0..7
    const int tk   = lane & 3;          // 0..3

    const int n = g_n[b];
    float* outb = out + (size_t)b * MAXN * DIM_OUT + (size_t)r0 * DIM_OUT;

    if (r0 >= n) {
        float4 zz = make_float4(0.f, 0.f, 0.f, 0.f);
        float4* o4 = (float4*)outb;
        #pragma unroll
        for (int e = 0; e < 8; ++e) o4[e * 256 + tid] = zz;
        return;
    }

    zs[tid] = z[(size_t)b * HID + tid];
    zs[256 + tid] = z[(size_t)b * HID + 256 + tid];
    __syncthreads();

    const float4* K4 = (const float4*)g_keys;
    const float4* Z4 = (const float4*)zs;

    // ---- build A: interleaved [kt][r][16]; thread handles float4 of consecutive k ----
    #pragma unroll
    for (int e = 0; e < 16; ++e) {
        int idx = e * 256 + tid;        // 0..4095
        int r = idx >> 7, q = idx & 127;   // q = k/4
        float4 kv = K4[(size_t)(r0 + r) * 128 + q];
        float4 zv = Z4[q];
        // k = 4q+j -> chunk kt=q>>2, p = 4j + (q&3)
        int base = (q >> 2) * 512 + r * 16 + (q & 3);
        As[base]      = tf32r(kv.x * zv.x);
        As[base + 4]  = tf32r(kv.y * zv.y);
        As[base + 8]  = tf32r(kv.z * zv.z);
        As[base + 12] = tf32r(kv.w * zv.w);
    }
    __syncthreads();   // A visible

    // ================= GEMM1: [32,512] @ W1 -> [32,384] =================
    float c1[2][6][4];
    #pragma unroll
    for (int i = 0; i < 2; ++i)
        #pragma unroll
        for (int jj = 0; jj < 6; ++jj)
            #pragma unroll
            for (int u = 0; u < 4; ++u) c1[i][jj][u] = 0.f;

    {
        const float* Wb = g_W1c + ((wc * 48 + tg) << 4) + (tk << 2);
        float4 bv[6], bn[6];
        #pragma unroll
        for (int jj = 0; jj < 6; ++jj)
            bv[jj] = __ldg((const float4*)(Wb + jj * 128));

        for (int kt = 0; kt < 32; ++kt) {
            if (kt + 1 < 32) {
                const float* Wn = Wb + (kt + 1) * 6144;
                #pragma unroll
                for (int jj = 0; jj < 6; ++jj)
                    bn[jj] = __ldg((const float4*)(Wn + jj * 128));
            }
            const float* Ab = As + kt * 512 + (tk << 2);
            uint32_t a[2][2][4];   // [k8 half][i][frag]
            #pragma unroll
            for (int i = 0; i < 2; ++i) {
                float4 fa = *(const float4*)(Ab + (i * 16 + tg) * 16);
                float4 fb = *(const float4*)(Ab + (i * 16 + tg + 8) * 16);
                a[0][i][0] = __float_as_uint(fa.x);
                a[0][i][1] = __float_as_uint(fb.x);
                a[0][i][2] = __float_as_uint(fa.y);
                a[0][i][3] = __float_as_uint(fb.y);
                a[1][i][0] = __float_as_uint(fa.z);
                a[1][i][1] = __float_as_uint(fb.z);
                a[1][i][2] = __float_as_uint(fa.w);
                a[1][i][3] = __float_as_uint(fb.w);
            }
            #pragma unroll
            for (int jj = 0; jj < 6; ++jj) {
                uint32_t b0 = __float_as_uint(bv[jj].x);
                uint32_t b1 = __float_as_uint(bv[jj].y);
                uint32_t b2 = __float_as_uint(bv[jj].z);
                uint32_t b3 = __float_as_uint(bv[jj].w);
                mma_tf32(c1[0][jj], a[0][0], b0, b1);
                mma_tf32(c1[1][jj], a[0][1], b0, b1);
                mma_tf32(c1[0][jj], a[1][0], b2, b3);
                mma_tf32(c1[1][jj], a[1][1], b2, b3);
            }
            #pragma unroll
            for (int jj = 0; jj < 6; ++jj) bv[jj] = bn[jj];
        }
    }
    __syncthreads();   // all A reads done -> region becomes H

    // ---- epilogue 1: +b1, mish, tf32, store H interleaved ----
    #pragma unroll
    for (int jj = 0; jj < 6; ++jj) {
        int col = wc * 48 + jj * 8 + 2 * tk;
        int kt = col >> 4, cc = col & 15;
        int p = 4 * (cc & 3) + (cc >> 2);
        float bx = __ldg(b1c + col), by = __ldg(b1c + col + 1);
        #pragma unroll
        for (int i = 0; i < 2; ++i) {
            int row = i * 16 + tg;
            float* H0 = Hs + kt * 512 + row * 16 + p;
            float* H1 = Hs + kt * 512 + (row + 8) * 16 + p;
            H0[0] = tf32r(mish_fast(c1[i][jj][0] + bx));
            H0[4] = tf32r(mish_fast(c1[i][jj][1] + by));
            H1[0] = tf32r(mish_fast(c1[i][jj][2] + bx));
            H1[4] = tf32r(mish_fast(c1[i][jj][3] + by));
        }
    }
    __syncthreads();   // H visible

    // ================= GEMM2: [32,384] @ W2 -> [32,256] =================
    float c2[2][4][4];
    #pragma unroll
    for (int i = 0; i < 2; ++i)
        #pragma unroll
        for (int jj = 0; jj < 4; ++jj)
            #pragma unroll
            for (int u = 0; u < 4; ++u) c2[i][jj][u] = 0.f;

    {
        const float* Wb = g_W2c + ((wc * 32 + tg) << 4) + (tk << 2);
        float4 bv[4], bn[4];
        #pragma unroll
        for (int jj = 0; jj < 4; ++jj)
            bv[jj] = __ldg((const float4*)(Wb + jj * 128));

        for (int kt = 0; kt < 24; ++kt) {
            if (kt + 1 < 24) {
                const float* Wn = Wb + (kt + 1) * 4096;
                #pragma unroll
                for (int jj = 0; jj < 4; ++jj)
                    bn[jj] = __ldg((const float4*)(Wn + jj * 128));
            }
            const float* Hb = Hs + kt * 512 + (tk << 2);
            uint32_t a[2][2][4];
            #pragma unroll
            for (int i = 0; i < 2; ++i) {
                float4 fa = *(const float4*)(Hb + (i * 16 + tg) * 16);
                float4 fb = *(const float4*)(Hb + (i * 16 + tg + 8) * 16);
                a[0][i][0] = __float_as_uint(fa.x);
                a[0][i][1] = __float_as_uint(fb.x);
                a[0][i][2] = __float_as_uint(fa.y);
                a[0][i][3] = __float_as_uint(fb.y);
                a[1][i][0] = __float_as_uint(fa.z);
                a[1][i][1] = __float_as_uint(fb.z);
                a[1][i][2] = __float_as_uint(fa.w);
                a[1][i][3] = __float_as_uint(fb.w);
            }
            #pragma unroll
            for (int jj = 0; jj < 4; ++jj) {
                uint32_t b0 = __float_as_uint(bv[jj].x);
                uint32_t b1 = __float_as_uint(bv[jj].y);
                uint32_t b2 = __float_as_uint(bv[jj].z);
                uint32_t b3 = __float_as_uint(bv[jj].w);
                mma_tf32(c2[0][jj], a[0][0], b0, b1);
                mma_tf32(c2[1][jj], a[0][1], b0, b1);
                mma_tf32(c2[0][jj], a[1][0], b2, b3);
                mma_tf32(c2[1][jj], a[1][1], b2, b3);
            }
            #pragma unroll
            for (int jj = 0; jj < 4; ++jj) bv[jj] = bn[jj];
        }
    }

    // ---- output: +b2, mask, store ----
    #pragma unroll
    for (int jj = 0; jj < 4; ++jj) {
        int col = wc * 32 + jj * 8 + 2 * tk;
        float bx = __ldg(b2c + col), by = __ldg(b2c + col + 1);
        #pragma unroll
        for (int i = 0; i < 2; ++i) {
            int row = i * 16 + tg;
            float2 o0, o1;
            bool v0 = (r0 + row) < n, v1 = (r0 + row + 8) < n;
            o0.x = v0 ? c2[i][jj][0] + bx : 0.f;
            o0.y = v0 ? c2[i][jj][1] + by : 0.f;
            o1.x = v1 ? c2[i][jj][2] + bx : 0.f;
            o1.y = v1 ? c2[i][jj][3] + by : 0.f;
            *(float2*)(outb + (size_t)row * DIM_OUT + col) = o0;
            *(float2*)(outb + (size_t)(row + 8) * DIM_OUT + col) = o1;
        }
    }
}

// ===================== launch =====================
extern "C" void kernel_launch(void* const* d_in, const int* in_sizes, int n_in,
                              void* d_out, int out_size)
{
    const float* z     = (const float*)d_in[0];
    const float* sp_W1 = (const float*)d_in[1];
    const float* sp_b1 = (const float*)d_in[2];
    const float* sp_g  = (const float*)d_in[3];
    const float* sp_be = (const float*)d_in[4];
    const float* sp_W2 = (const float*)d_in[5];
    const float* sp_b2 = (const float*)d_in[6];
    const float* kn_W1 = (const float*)d_in[7];
    const float* kn_b1 = (const float*)d_in[8];
    const float* kn_g  = (const float*)d_in[9];
    const float* kn_be = (const float*)d_in[10];
    const float* kn_W2 = (const float*)d_in[11];
    const float* kn_b2 = (const float*)d_in[12];
    const float* de_W1 = (const float*)d_in[13];
    const float* de_b1 = (const float*)d_in[14];
    const float* de_W2 = (const float*)d_in[15];
    const float* de_b2 = (const float*)d_in[16];
    float* out = (float*)d_out;

    long long osz = (long long)out_size;
    int write_n    = (osz >= X_SIZE + B_DIM) ? 1 : 0;
    int write_mask = (osz >= X_SIZE + B_DIM + (long long)B_DIM * MAXN) ? 1 : 0;

    cudaFuncSetAttribute(decoder_kernel,
                         cudaFuncAttributeMaxDynamicSharedMemorySize,
                         DEC_SMEM_BYTES);

    sizepred_kernel<<<512, 256>>>(z, sp_W1, sp_b1, sp_g, sp_be, sp_W2, sp_b2,
                                  out, write_n, write_mask);
    keys_kernel<<<128, 512>>>(kn_W1, kn_b1, kn_g, kn_be, kn_W2, kn_b2);
    prep_kernel<<<1152, 256>>>(de_W1, de_W2);
    decoder_kernel<<<B_DIM * 4, 256, DEC_SMEM_BYTES>>>(z, de_b1, de_b2, out);
}

// round 10
// speedup vs baseline: 1.1765x; 1.1765x over previous
#include <cuda_runtime.h>
#include <math.h>
#include <cstdint>

#define B_DIM   2048
#define HID     512
#define DIM_OUT 256
#define MAXN    128
#define MID_S   256
#define MID_K   320
#define MID_D   384

#define X_SIZE  (2048LL*128*256)
#define N_OFF   X_SIZE
#define MASK_OFF (X_SIZE + 2048LL)

__device__ __align__(16) float g_keys[MAXN * HID];
__device__ int   g_n[B_DIM];
// W1^T k16-interleaved: [32 chunks][384 n][16]  (pos p holds k = 4*(p%4)+p/4)
__device__ __align__(16) float g_W1c[32 * 384 * 16];
// W2^T k16-interleaved: [24 chunks][256 n][16]
__device__ __align__(16) float g_W2c[24 * 256 * 16];

__device__ __forceinline__ float mishf(float x) {
    float sp = fmaxf(x, 0.f) + log1pf(expf(-fabsf(x)));
    return x * tanhf(sp);
}
__device__ __forceinline__ float mish_fast(float x) {
    float e = __expf(x);
    float y = 1.f + e;
    float d = fmaf(y, y, 1.f);
    return x - 2.f * x * __frcp_rn(d);
}
__device__ __forceinline__ float tf32r(float x) {
    uint32_t u;
    asm("cvt.rna.tf32.f32 %0, %1;" : "=r"(u) : "f"(x));
    return __uint_as_float(u);
}
__device__ __forceinline__ void mma_tf32(float* c, const uint32_t* a,
                                         uint32_t b0, uint32_t b1) {
    asm volatile(
        "mma.sync.aligned.m16n8k8.row.col.f32.tf32.tf32.f32 "
        "{%0,%1,%2,%3}, {%4,%5,%6,%7}, {%8,%9}, {%0,%1,%2,%3};"
        : "+f"(c[0]), "+f"(c[1]), "+f"(c[2]), "+f"(c[3])
        : "r"(a[0]), "r"(a[1]), "r"(a[2]), "r"(a[3]), "r"(b0), "r"(b1));
}

// ===================== Kernel A: size_pred (4 rows/block) =====================
__global__ __launch_bounds__(256)
void sizepred_kernel(const float* __restrict__ z,
                     const float* __restrict__ W1, const float* __restrict__ b1,
                     const float* __restrict__ g,  const float* __restrict__ be,
                     const float* __restrict__ W2, const float* __restrict__ b2,
                     float* __restrict__ out, int write_n, int write_mask)
{
    __shared__ float zsh[4][HID];
    __shared__ float hsh[4][MID_S];
    __shared__ float smean[4], srstd[4];
    __shared__ int   nsh[4];
    const int b0  = blockIdx.x * 4;
    const int tid = threadIdx.x;

    #pragma unroll
    for (int e = 0; e < 8; ++e) {
        int lin = e * 256 + tid;
        int bb = lin >> 9, i = lin & 511;
        zsh[bb][i] = z[(size_t)(b0 + bb) * HID + i];
    }
    __syncthreads();

    const int j = tid;
    float acc[4];
    {
        float bj = b1[j];
        #pragma unroll
        for (int bb = 0; bb < 4; ++bb) acc[bb] = bj;
    }
    for (int i = 0; i < HID; i += 8) {
        #pragma unroll
        for (int ii = 0; ii < 8; ++ii) {
            float w = W1[(size_t)(i + ii) * MID_S + j];
            #pragma unroll
            for (int bb = 0; bb < 4; ++bb)
                acc[bb] = fmaf(zsh[bb][i + ii], w, acc[bb]);
        }
    }
    #pragma unroll
    for (int bb = 0; bb < 4; ++bb) hsh[bb][j] = acc[bb];
    __syncthreads();

    const int wrow = (tid >> 5) & 3, lane = tid & 31;
    {
        float s = 0.f, s2 = 0.f;
        for (int jj = lane; jj < MID_S; jj += 32) {
            float v = hsh[wrow][jj];
            s += v; s2 += v * v;
        }
        #pragma unroll
        for (int o = 16; o; o >>= 1) {
            s  += __shfl_xor_sync(0xffffffffu, s,  o);
            s2 += __shfl_xor_sync(0xffffffffu, s2, o);
        }
        if (lane == 0) {
            float m = s * (1.f / MID_S);
            float var = s2 * (1.f / MID_S) - m * m;
            smean[wrow] = m;
            srstd[wrow] = rsqrtf(var + 1e-5f);
        }
    }
    __syncthreads();

    {
        float gj = g[j], bej = be[j], w2j = W2[j];
        #pragma unroll
        for (int bb = 0; bb < 4; ++bb) {
            float v = (acc[bb] - smean[bb]) * srstd[bb] * gj + bej;
            hsh[bb][j] = mishf(v) * w2j;
        }
    }
    __syncthreads();

    {
        float s = 0.f;
        for (int jj = lane; jj < MID_S; jj += 32) s += hsh[wrow][jj];
        #pragma unroll
        for (int o = 16; o; o >>= 1) s += __shfl_xor_sync(0xffffffffu, s, o);
        if (lane == 0) {
            float logit = s + b2[0];
            float nf = fminf(fmaxf(rintf(logit), 0.f), (float)MAXN);
            int ni = (int)nf;
            g_n[b0 + wrow] = ni;
            nsh[wrow] = ni;
            if (write_n) out[N_OFF + b0 + wrow] = nf;
        }
    }
    __syncthreads();

    if (write_mask) {
        #pragma unroll
        for (int e = 0; e < 2; ++e) {
            int lin = e * 256 + tid;
            int bb = lin >> 7, kk = lin & 127;
            out[MASK_OFF + (size_t)(b0 + bb) * MAXN + kk] = (kk < nsh[bb]) ? 1.f : 0.f;
        }
    }
}

// ===================== Kernel B: keys =====================
__global__ __launch_bounds__(512)
void keys_kernel(const float* __restrict__ W1, const float* __restrict__ b1,
                 const float* __restrict__ g,  const float* __restrict__ be,
                 const float* __restrict__ W2, const float* __restrict__ b2)
{
    __shared__ float hs[MID_K];
    __shared__ float warp_s[16], warp_s2[16];
    __shared__ float st_mean, st_rstd;
    const int k = blockIdx.x;
    const int tid = threadIdx.x;
    const bool act = tid < MID_K;
    float v = 0.f;
    if (act) v = W1[(size_t)k * MID_K + tid] + b1[tid];
    float s = v, s2 = v * v;
    #pragma unroll
    for (int o = 16; o; o >>= 1) {
        s  += __shfl_xor_sync(0xffffffffu, s,  o);
        s2 += __shfl_xor_sync(0xffffffffu, s2, o);
    }
    const int wid = tid >> 5, lane = tid & 31;
    if (lane == 0) { warp_s[wid] = s; warp_s2[wid] = s2; }
    __syncthreads();
    if (wid == 0) {
        float ps  = (lane < 16) ? warp_s[lane]  : 0.f;
        float ps2 = (lane < 16) ? warp_s2[lane] : 0.f;
        #pragma unroll
        for (int o = 8; o; o >>= 1) {
            ps  += __shfl_xor_sync(0xffffffffu, ps,  o);
            ps2 += __shfl_xor_sync(0xffffffffu, ps2, o);
        }
        if (lane == 0) {
            float m = ps * (1.f / MID_K);
            float var = ps2 * (1.f / MID_K) - m * m;
            st_mean = m;
            st_rstd = rsqrtf(var + 1e-5f);
        }
    }
    __syncthreads();
    if (act) hs[tid] = mishf((v - st_mean) * st_rstd * g[tid] + be[tid]);
    __syncthreads();
    const int o = tid;
    float acc = b2[o];
    for (int jj = 0; jj < MID_K; jj += 4) {
        #pragma unroll
        for (int u = 0; u < 4; ++u)
            acc = fmaf(hs[jj + u], W2[(size_t)(jj + u) * HID + o], acc);
    }
    g_keys[(size_t)k * HID + o] = acc;
}

// ===================== Prep: k16-interleaved transposed tf32 weights =====================
#define W1C_TOTAL (32 * 384 * 16)   // 196608
#define W2C_TOTAL (24 * 256 * 16)   // 98304
__global__ __launch_bounds__(256)
void prep_kernel(const float* __restrict__ W1, const float* __restrict__ W2)
{
    int id = blockIdx.x * 256 + threadIdx.x;
    if (id < W1C_TOTAL) {
        int kt = id / 6144, rem = id % 6144;
        int nn = rem >> 4, p = rem & 15;
        int ko = 4 * (p & 3) + (p >> 2);
        g_W1c[id] = tf32r(W1[(size_t)(kt * 16 + ko) * MID_D + nn]);
    } else if (id < W1C_TOTAL + W2C_TOTAL) {
        int t = id - W1C_TOTAL;
        int kt = t / 4096, rem = t % 4096;
        int nn = rem >> 4, p = rem & 15;
        int ko = 4 * (p & 3) + (p >> 2);
        g_W2c[t] = tf32r(W2[(size_t)(kt * 16 + ko) * DIM_OUT + nn]);
    }
}

// ===================== Kernel C: 32-row-chunk tf32 decoder, 2 CTAs/SM =====================
#define A_STRIDE 516
#define H_STRIDE 388
#define OFF_Z_FLOATS (32 * A_STRIDE)               // 16512
#define DEC_SMEM_BYTES ((OFF_Z_FLOATS + 512) * 4)  // 68096

__global__ __launch_bounds__(256, 2)
void decoder_kernel(const float* __restrict__ z,
                    const float* __restrict__ b1c,
                    const float* __restrict__ b2c,
                    float* __restrict__ out)
{
    extern __shared__ float sm[];
    float* As = sm;
    float* Hs = sm;
    float* zs = sm + OFF_Z_FLOATS;

    const int b    = blockIdx.x >> 2;
    const int r0   = (blockIdx.x & 3) * 32;
    const int tid  = threadIdx.x;
    const int wc   = tid >> 5;          // 0..7 warp col
    const int lane = tid & 31;
    const int tg   = lane >> 2;         // 0..7
    const int tk   = lane & 3;          // 0..3

    const int n = g_n[b];
    float* outb = out + (size_t)b * MAXN * DIM_OUT + (size_t)r0 * DIM_OUT;

    if (r0 >= n) {
        float4 zz = make_float4(0.f, 0.f, 0.f, 0.f);
        float4* o4 = (float4*)outb;
        #pragma unroll
        for (int e = 0; e < 8; ++e) o4[e * 256 + tid] = zz;
        return;
    }

    zs[tid] = z[(size_t)b * HID + tid];
    zs[256 + tid] = z[(size_t)b * HID + 256 + tid];
    __syncthreads();

    const float4* K4 = (const float4*)g_keys;
    const float4* Z4 = (const float4*)zs;

    // ---- build A[r][k] = tf32(keys[r0+r][k] * z[k]), stride 516 ----
    #pragma unroll
    for (int e = 0; e < 16; ++e) {
        int idx = e * 256 + tid;        // 0..4095
        int r = idx >> 7, q = idx & 127;
        float4 kv = K4[(size_t)(r0 + r) * 128 + q];
        float4 zv = Z4[q];
        float4 av;
        av.x = tf32r(kv.x * zv.x);
        av.y = tf32r(kv.y * zv.y);
        av.z = tf32r(kv.z * zv.z);
        av.w = tf32r(kv.w * zv.w);
        *(float4*)(As + r * A_STRIDE + q * 4) = av;
    }
    __syncthreads();   // A visible

    // ================= GEMM1: [32,512] @ W1 -> [32,384] =================
    float c1[2][6][4];
    #pragma unroll
    for (int i = 0; i < 2; ++i)
        #pragma unroll
        for (int jj = 0; jj < 6; ++jj)
            #pragma unroll
            for (int u = 0; u < 4; ++u) c1[i][jj][u] = 0.f;

    {
        const float* Wb = g_W1c + ((wc * 48 + tg) << 4) + (tk << 2);
        float4 bv[6], bn[6];
        #pragma unroll
        for (int jj = 0; jj < 6; ++jj)
            bv[jj] = __ldg((const float4*)(Wb + jj * 128));

        for (int kt = 0; kt < 32; ++kt) {
            // A-frag LDS first (29-cyc latency hides under LDG issue below)
            const int k0 = kt << 4;
            uint32_t a[2][2][4];   // [k8 half][i][frag]
            #pragma unroll
            for (int i = 0; i < 2; ++i) {
                const float* Ar = As + (i * 16 + tg) * A_STRIDE + k0 + tk;
                a[0][i][0] = __float_as_uint(Ar[0]);
                a[0][i][1] = __float_as_uint(Ar[8 * A_STRIDE]);
                a[0][i][2] = __float_as_uint(Ar[4]);
                a[0][i][3] = __float_as_uint(Ar[8 * A_STRIDE + 4]);
                a[1][i][0] = __float_as_uint(Ar[8]);
                a[1][i][1] = __float_as_uint(Ar[8 * A_STRIDE + 8]);
                a[1][i][2] = __float_as_uint(Ar[12]);
                a[1][i][3] = __float_as_uint(Ar[8 * A_STRIDE + 12]);
            }
            if (kt + 1 < 32) {
                const float* Wn = Wb + (kt + 1) * 6144;
                #pragma unroll
                for (int jj = 0; jj < 6; ++jj)
                    bn[jj] = __ldg((const float4*)(Wn + jj * 128));
            }
            // k8-half 0 across all jj, then half 1: dependent-MMA distance = 12
            #pragma unroll
            for (int jj = 0; jj < 6; ++jj) {
                mma_tf32(c1[0][jj], a[0][0],
                         __float_as_uint(bv[jj].x), __float_as_uint(bv[jj].y));
                mma_tf32(c1[1][jj], a[0][1],
                         __float_as_uint(bv[jj].x), __float_as_uint(bv[jj].y));
            }
            #pragma unroll
            for (int jj = 0; jj < 6; ++jj) {
                mma_tf32(c1[0][jj], a[1][0],
                         __float_as_uint(bv[jj].z), __float_as_uint(bv[jj].w));
                mma_tf32(c1[1][jj], a[1][1],
                         __float_as_uint(bv[jj].z), __float_as_uint(bv[jj].w));
            }
            #pragma unroll
            for (int jj = 0; jj < 6; ++jj) bv[jj] = bn[jj];
        }
    }
    __syncthreads();   // all A reads done -> region becomes H

    // ---- epilogue 1: +b1, mish, tf32, store H (stride 388) ----
    #pragma unroll
    for (int jj = 0; jj < 6; ++jj) {
        int col = wc * 48 + jj * 8 + 2 * tk;
        float bx = __ldg(b1c + col), by = __ldg(b1c + col + 1);
        #pragma unroll
        for (int i = 0; i < 2; ++i) {
            int row = i * 16 + tg;
            float2 v0, v1;
            v0.x = tf32r(mish_fast(c1[i][jj][0] + bx));
            v0.y = tf32r(mish_fast(c1[i][jj][1] + by));
            v1.x = tf32r(mish_fast(c1[i][jj][2] + bx));
            v1.y = tf32r(mish_fast(c1[i][jj][3] + by));
            *(float2*)(Hs + row * H_STRIDE + col) = v0;
            *(float2*)(Hs + (row + 8) * H_STRIDE + col) = v1;
        }
    }
    __syncthreads();   // H visible

    // ================= GEMM2: [32,384] @ W2 -> [32,256] =================
    float c2[2][4][4];
    #pragma unroll
    for (int i = 0; i < 2; ++i)
        #pragma unroll
        for (int jj = 0; jj < 4; ++jj)
            #pragma unroll
            for (int u = 0; u < 4; ++u) c2[i][jj][u] = 0.f;

    {
        const float* Wb = g_W2c + ((wc * 32 + tg) << 4) + (tk << 2);
        float4 bv[4], bn[4];
        #pragma unroll
        for (int jj = 0; jj < 4; ++jj)
            bv[jj] = __ldg((const float4*)(Wb + jj * 128));

        for (int kt = 0; kt < 24; ++kt) {
            const int k0 = kt << 4;
            uint32_t a[2][2][4];
            #pragma unroll
            for (int i = 0; i < 2; ++i) {
                const float* Hr = Hs + (i * 16 + tg) * H_STRIDE + k0 + tk;
                a[0][i][0] = __float_as_uint(Hr[0]);
                a[0][i][1] = __float_as_uint(Hr[8 * H_STRIDE]);
                a[0][i][2] = __float_as_uint(Hr[4]);
                a[0][i][3] = __float_as_uint(Hr[8 * H_STRIDE + 4]);
                a[1][i][0] = __float_as_uint(Hr[8]);
                a[1][i][1] = __float_as_uint(Hr[8 * H_STRIDE + 8]);
                a[1][i][2] = __float_as_uint(Hr[12]);
                a[1][i][3] = __float_as_uint(Hr[8 * H_STRIDE + 12]);
            }
            if (kt + 1 < 24) {
                const float* Wn = Wb + (kt + 1) * 4096;
                #pragma unroll
                for (int jj = 0; jj < 4; ++jj)
                    bn[jj] = __ldg((const float4*)(Wn + jj * 128));
            }
            #pragma unroll
            for (int jj = 0; jj < 4; ++jj) {
                mma_tf32(c2[0][jj], a[0][0],
                         __float_as_uint(bv[jj].x), __float_as_uint(bv[jj].y));
                mma_tf32(c2[1][jj], a[0][1],
                         __float_as_uint(bv[jj].x), __float_as_uint(bv[jj].y));
            }
            #pragma unroll
            for (int jj = 0; jj < 4; ++jj) {
                mma_tf32(c2[0][jj], a[1][0],
                         __float_as_uint(bv[jj].z), __float_as_uint(bv[jj].w));
                mma_tf32(c2[1][jj], a[1][1],
                         __float_as_uint(bv[jj].z), __float_as_uint(bv[jj].w));
            }
            #pragma unroll
            for (int jj = 0; jj < 4; ++jj) bv[jj] = bn[jj];
        }
    }

    // ---- output: +b2, mask, store ----
    #pragma unroll
    for (int jj = 0; jj < 4; ++jj) {
        int col = wc * 32 + jj * 8 + 2 * tk;
        float bx = __ldg(b2c + col), by = __ldg(b2c + col + 1);
        #pragma unroll
        for (int i = 0; i < 2; ++i) {
            int row = i * 16 + tg;
            float2 o0, o1;
            bool v0 = (r0 + row) < n, v1 = (r0 + row + 8) < n;
            o0.x = v0 ? c2[i][jj][0] + bx : 0.f;
            o0.y = v0 ? c2[i][jj][1] + by : 0.f;
            o1.x = v1 ? c2[i][jj][2] + bx : 0.f;
            o1.y = v1 ? c2[i][jj][3] + by : 0.f;
            *(float2*)(outb + (size_t)row * DIM_OUT + col) = o0;
            *(float2*)(outb + (size_t)(row + 8) * DIM_OUT + col) = o1;
        }
    }
}

// ===================== launch =====================
extern "C" void kernel_launch(void* const* d_in, const int* in_sizes, int n_in,
                              void* d_out, int out_size)
{
    const float* z     = (const float*)d_in[0];
    const float* sp_W1 = (const float*)d_in[1];
    const float* sp_b1 = (const float*)d_in[2];
    const float* sp_g  = (const float*)d_in[3];
    const float* sp_be = (const float*)d_in[4];
    const float* sp_W2 = (const float*)d_in[5];
    const float* sp_b2 = (const float*)d_in[6];
    const float* kn_W1 = (const float*)d_in[7];
    const float* kn_b1 = (const float*)d_in[8];
    const float* kn_g  = (const float*)d_in[9];
    const float* kn_be = (const float*)d_in[10];
    const float* kn_W2 = (const float*)d_in[11];
    const float* kn_b2 = (const float*)d_in[12];
    const float* de_W1 = (const float*)d_in[13];
    const float* de_b1 = (const float*)d_in[14];
    const float* de_W2 = (const float*)d_in[15];
    const float* de_b2 = (const float*)d_in[16];
    float* out = (float*)d_out;

    long long osz = (long long)out_size;
    int write_n    = (osz >= X_SIZE + B_DIM) ? 1 : 0;
    int write_mask = (osz >= X_SIZE + B_DIM + (long long)B_DIM * MAXN) ? 1 : 0;

    cudaFuncSetAttribute(decoder_kernel,
                         cudaFuncAttributeMaxDynamicSharedMemorySize,
                         DEC_SMEM_BYTES);

    sizepred_kernel<<<512, 256>>>(z, sp_W1, sp_b1, sp_g, sp_be, sp_W2, sp_b2,
                                  out, write_n, write_mask);
    keys_kernel<<<128, 512>>>(kn_W1, kn_b1, kn_g, kn_be, kn_W2, kn_b2);
    prep_kernel<<<1152, 256>>>(de_W1, de_W2);
    decoder_kernel<<<B_DIM * 4, 256, DEC_SMEM_BYTES>>>(z, de_b1, de_b2, out);
}

// round 11
// speedup vs baseline: 1.8213x; 1.5480x over previous
#include <cuda_runtime.h>
#include <cuda_fp16.h>
#include <math.h>
#include <cstdint>

#define B_DIM   2048
#define HID     512
#define DIM_OUT 256
#define MAXN    128
#define MID_S   256
#define MID_K   320
#define MID_D   384

#define X_SIZE  (2048LL*128*256)
#define N_OFF   X_SIZE
#define MASK_OFF (X_SIZE + 2048LL)

__device__ __align__(16) float g_keys[MAXN * HID];
__device__ int   g_n[B_DIM];
// W1^T fp16, k32 chunks, lane-group interleaved:
// [16 ktp][384 n][32 halves]; halves[tk*8+pos]: hi=pos>>2, sub=pos&3,
// k = ktp*32 + hi*16 + (sub<2 ? 2tk+sub : 2tk+8+sub-2)
__device__ __align__(16) __half g_W1h[16 * 384 * 32];
// W2^T fp16: [12 ktp][256 n][32 halves], same scheme
__device__ __align__(16) __half g_W2h[12 * 256 * 32];

__device__ __forceinline__ float mishf(float x) {
    float sp = fmaxf(x, 0.f) + log1pf(expf(-fabsf(x)));
    return x * tanhf(sp);
}
__device__ __forceinline__ float mish_fast(float x) {
    float e = __expf(x);
    float y = 1.f + e;
    float d = fmaf(y, y, 1.f);
    return x - 2.f * x * __frcp_rn(d);
}
__device__ __forceinline__ void mma_f16(float* c, const uint32_t* a,
                                        uint32_t b0, uint32_t b1) {
    asm volatile(
        "mma.sync.aligned.m16n8k16.row.col.f32.f16.f16.f32 "
        "{%0,%1,%2,%3}, {%4,%5,%6,%7}, {%8,%9}, {%0,%1,%2,%3};"
        : "+f"(c[0]), "+f"(c[1]), "+f"(c[2]), "+f"(c[3])
        : "r"(a[0]), "r"(a[1]), "r"(a[2]), "r"(a[3]), "r"(b0), "r"(b1));
}

// ===================== Kernel A: size_pred (4 rows/block) =====================
__global__ __launch_bounds__(256)
void sizepred_kernel(const float* __restrict__ z,
                     const float* __restrict__ W1, const float* __restrict__ b1,
                     const float* __restrict__ g,  const float* __restrict__ be,
                     const float* __restrict__ W2, const float* __restrict__ b2,
                     float* __restrict__ out, int write_n, int write_mask)
{
    __shared__ float zsh[4][HID];
    __shared__ float hsh[4][MID_S];
    __shared__ float smean[4], srstd[4];
    __shared__ int   nsh[4];
    const int b0  = blockIdx.x * 4;
    const int tid = threadIdx.x;

    #pragma unroll
    for (int e = 0; e < 8; ++e) {
        int lin = e * 256 + tid;
        int bb = lin >> 9, i = lin & 511;
        zsh[bb][i] = z[(size_t)(b0 + bb) * HID + i];
    }
    __syncthreads();

    const int j = tid;
    float acc[4];
    {
        float bj = b1[j];
        #pragma unroll
        for (int bb = 0; bb < 4; ++bb) acc[bb] = bj;
    }
    for (int i = 0; i < HID; i += 8) {
        #pragma unroll
        for (int ii = 0; ii < 8; ++ii) {
            float w = W1[(size_t)(i + ii) * MID_S + j];
            #pragma unroll
            for (int bb = 0; bb < 4; ++bb)
                acc[bb] = fmaf(zsh[bb][i + ii], w, acc[bb]);
        }
    }
    #pragma unroll
    for (int bb = 0; bb < 4; ++bb) hsh[bb][j] = acc[bb];
    __syncthreads();

    const int wrow = (tid >> 5) & 3, lane = tid & 31;
    {
        float s = 0.f, s2 = 0.f;
        for (int jj = lane; jj < MID_S; jj += 32) {
            float v = hsh[wrow][jj];
            s += v; s2 += v * v;
        }
        #pragma unroll
        for (int o = 16; o; o >>= 1) {
            s  += __shfl_xor_sync(0xffffffffu, s,  o);
            s2 += __shfl_xor_sync(0xffffffffu, s2, o);
        }
        if (lane == 0) {
            float m = s * (1.f / MID_S);
            float var = s2 * (1.f / MID_S) - m * m;
            smean[wrow] = m;
            srstd[wrow] = rsqrtf(var + 1e-5f);
        }
    }
    __syncthreads();

    {
        float gj = g[j], bej = be[j], w2j = W2[j];
        #pragma unroll
        for (int bb = 0; bb < 4; ++bb) {
            float v = (acc[bb] - smean[bb]) * srstd[bb] * gj + bej;
            hsh[bb][j] = mishf(v) * w2j;
        }
    }
    __syncthreads();

    {
        float s = 0.f;
        for (int jj = lane; jj < MID_S; jj += 32) s += hsh[wrow][jj];
        #pragma unroll
        for (int o = 16; o; o >>= 1) s += __shfl_xor_sync(0xffffffffu, s, o);
        if (lane == 0) {
            float logit = s + b2[0];
            float nf = fminf(fmaxf(rintf(logit), 0.f), (float)MAXN);
            int ni = (int)nf;
            g_n[b0 + wrow] = ni;
            nsh[wrow] = ni;
            if (write_n) out[N_OFF + b0 + wrow] = nf;
        }
    }
    __syncthreads();

    if (write_mask) {
        #pragma unroll
        for (int e = 0; e < 2; ++e) {
            int lin = e * 256 + tid;
            int bb = lin >> 7, kk = lin & 127;
            out[MASK_OFF + (size_t)(b0 + bb) * MAXN + kk] = (kk < nsh[bb]) ? 1.f : 0.f;
        }
    }
}

// ===================== Kernel B: keys =====================
__global__ __launch_bounds__(512)
void keys_kernel(const float* __restrict__ W1, const float* __restrict__ b1,
                 const float* __restrict__ g,  const float* __restrict__ be,
                 const float* __restrict__ W2, const float* __restrict__ b2)
{
    __shared__ float hs[MID_K];
    __shared__ float warp_s[16], warp_s2[16];
    __shared__ float st_mean, st_rstd;
    const int k = blockIdx.x;
    const int tid = threadIdx.x;
    const bool act = tid < MID_K;
    float v = 0.f;
    if (act) v = W1[(size_t)k * MID_K + tid] + b1[tid];
    float s = v, s2 = v * v;
    #pragma unroll
    for (int o = 16; o; o >>= 1) {
        s  += __shfl_xor_sync(0xffffffffu, s,  o);
        s2 += __shfl_xor_sync(0xffffffffu, s2, o);
    }
    const int wid = tid >> 5, lane = tid & 31;
    if (lane == 0) { warp_s[wid] = s; warp_s2[wid] = s2; }
    __syncthreads();
    if (wid == 0) {
        float ps  = (lane < 16) ? warp_s[lane]  : 0.f;
        float ps2 = (lane < 16) ? warp_s2[lane] : 0.f;
        #pragma unroll
        for (int o = 8; o; o >>= 1) {
            ps  += __shfl_xor_sync(0xffffffffu, ps,  o);
            ps2 += __shfl_xor_sync(0xffffffffu, ps2, o);
        }
        if (lane == 0) {
            float m = ps * (1.f / MID_K);
            float var = ps2 * (1.f / MID_K) - m * m;
            st_mean = m;
            st_rstd = rsqrtf(var + 1e-5f);
        }
    }
    __syncthreads();
    if (act) hs[tid] = mishf((v - st_mean) * st_rstd * g[tid] + be[tid]);
    __syncthreads();
    const int o = tid;
    float acc = b2[o];
    for (int jj = 0; jj < MID_K; jj += 4) {
        #pragma unroll
        for (int u = 0; u < 4; ++u)
            acc = fmaf(hs[jj + u], W2[(size_t)(jj + u) * HID + o], acc);
    }
    g_keys[(size_t)k * HID + o] = acc;
}

// ===================== Prep: fp16 interleaved transposed weights =====================
#define W1H_TOTAL (16 * 384 * 32)   // 196608
#define W2H_TOTAL (12 * 256 * 32)   // 98304
__global__ __launch_bounds__(256)
void prep_kernel(const float* __restrict__ W1, const float* __restrict__ W2)
{
    int id = blockIdx.x * 256 + threadIdx.x;
    if (id < W1H_TOTAL) {
        int ktp = id / 12288, rem = id % 12288;
        int nn = rem >> 5, h = rem & 31;
        int tk = h >> 3, pos = h & 7;
        int sub = pos & 3;
        int kl = ((pos >> 2) << 4) + ((sub < 2) ? (2 * tk + sub) : (2 * tk + 8 + sub - 2));
        g_W1h[id] = __float2half_rn(W1[(size_t)(ktp * 32 + kl) * MID_D + nn]);
    } else if (id < W1H_TOTAL + W2H_TOTAL) {
        int t = id - W1H_TOTAL;
        int ktp = t / 8192, rem = t % 8192;
        int nn = rem >> 5, h = rem & 31;
        int tk = h >> 3, pos = h & 7;
        int sub = pos & 3;
        int kl = ((pos >> 2) << 4) + ((sub < 2) ? (2 * tk + sub) : (2 * tk + 8 + sub - 2));
        g_W2h[t] = __float2half_rn(W2[(size_t)(ktp * 32 + kl) * DIM_OUT + nn]);
    }
}

// ===================== Kernel C: fp16 mma decoder, 2 CTAs/SM =====================
// A smem: [32 rows][520 halves] fp16 (1040 B/row; 260 words %32 = 4 -> frag
// LDS banks {4*tg+tk} conflict-free). H aliased: [32][392 halves].
#define A_STR 520
#define H_STR 392
#define ZS_BYTE_OFF 33280                    // 32*520*2
#define DEC_SMEM_BYTES (ZS_BYTE_OFF + 2048)  // 35328

__global__ __launch_bounds__(256, 2)
void decoder_kernel(const float* __restrict__ z,
                    const float* __restrict__ b1c,
                    const float* __restrict__ b2c,
                    float* __restrict__ out)
{
    extern __shared__ char smraw[];
    __half* Ah = (__half*)smraw;
    __half* Hh = (__half*)smraw;
    float*  zs = (float*)(smraw + ZS_BYTE_OFF);

    const int b    = blockIdx.x >> 2;
    const int r0   = (blockIdx.x & 3) * 32;
    const int tid  = threadIdx.x;
    const int wc   = tid >> 5;          // 0..7 warp col
    const int lane = tid & 31;
    const int tg   = lane >> 2;         // 0..7
    const int tk   = lane & 3;          // 0..3

    const int n = g_n[b];
    float* outb = out + (size_t)b * MAXN * DIM_OUT + (size_t)r0 * DIM_OUT;

    if (r0 >= n) {
        float4 zz = make_float4(0.f, 0.f, 0.f, 0.f);
        float4* o4 = (float4*)outb;
        #pragma unroll
        for (int e = 0; e < 8; ++e) o4[e * 256 + tid] = zz;
        return;
    }

    zs[tid] = z[(size_t)b * HID + tid];
    zs[256 + tid] = z[(size_t)b * HID + 256 + tid];
    __syncthreads();

    const float4* K4 = (const float4*)g_keys;
    const float4* Z4 = (const float4*)zs;

    // ---- build A (fp16): A[r][k] = half(keys[r0+r][k] * z[k]) ----
    #pragma unroll
    for (int e = 0; e < 16; ++e) {
        int idx = e * 256 + tid;        // 0..4095
        int r = idx >> 7, q = idx & 127;
        float4 kv = K4[(size_t)(r0 + r) * 128 + q];
        float4 zv = Z4[q];
        __half2 h0 = __floats2half2_rn(kv.x * zv.x, kv.y * zv.y);
        __half2 h1 = __floats2half2_rn(kv.z * zv.z, kv.w * zv.w);
        uint2 pk;
        pk.x = *(uint32_t*)&h0;
        pk.y = *(uint32_t*)&h1;
        *(uint2*)(Ah + r * A_STR + q * 4) = pk;
    }
    __syncthreads();   // A visible

    // ================= GEMM1: [32,512] @ W1 -> [32,384] =================
    float c1[2][6][4];
    #pragma unroll
    for (int i = 0; i < 2; ++i)
        #pragma unroll
        for (int jj = 0; jj < 6; ++jj)
            #pragma unroll
            for (int u = 0; u < 4; ++u) c1[i][jj][u] = 0.f;

    {
        const __half* Wb = g_W1h + ((wc * 48 + tg) << 5) + (tk << 3);
        uint4 bv[6], bn[6];
        #pragma unroll
        for (int jj = 0; jj < 6; ++jj)
            bv[jj] = *(const uint4*)(Wb + jj * 256);

        for (int ktp = 0; ktp < 16; ++ktp) {
            const int k0 = ktp << 5;
            // A frags, first k16
            uint32_t ae[2][4];
            #pragma unroll
            for (int i = 0; i < 2; ++i) {
                const __half* Ar = Ah + (i * 16 + tg) * A_STR + k0 + 2 * tk;
                ae[i][0] = *(const uint32_t*)(Ar);
                ae[i][1] = *(const uint32_t*)(Ar + 8 * A_STR);
                ae[i][2] = *(const uint32_t*)(Ar + 8);
                ae[i][3] = *(const uint32_t*)(Ar + 8 * A_STR + 8);
            }
            if (ktp + 1 < 16) {
                const __half* Wn = Wb + (ktp + 1) * 12288;
                #pragma unroll
                for (int jj = 0; jj < 6; ++jj)
                    bn[jj] = *(const uint4*)(Wn + jj * 256);
            }
            #pragma unroll
            for (int jj = 0; jj < 6; ++jj) {
                mma_f16(c1[0][jj], ae[0], bv[jj].x, bv[jj].y);
                mma_f16(c1[1][jj], ae[1], bv[jj].x, bv[jj].y);
            }
            // A frags, second k16
            uint32_t ao[2][4];
            #pragma unroll
            for (int i = 0; i < 2; ++i) {
                const __half* Ar = Ah + (i * 16 + tg) * A_STR + k0 + 16 + 2 * tk;
                ao[i][0] = *(const uint32_t*)(Ar);
                ao[i][1] = *(const uint32_t*)(Ar + 8 * A_STR);
                ao[i][2] = *(const uint32_t*)(Ar + 8);
                ao[i][3] = *(const uint32_t*)(Ar + 8 * A_STR + 8);
            }
            #pragma unroll
            for (int jj = 0; jj < 6; ++jj) {
                mma_f16(c1[0][jj], ao[0], bv[jj].z, bv[jj].w);
                mma_f16(c1[1][jj], ao[1], bv[jj].z, bv[jj].w);
            }
            #pragma unroll
            for (int jj = 0; jj < 6; ++jj) bv[jj] = bn[jj];
        }
    }
    __syncthreads();   // all A reads done -> region becomes H

    // ---- epilogue 1: +b1, mish, fp16, store H ----
    #pragma unroll
    for (int jj = 0; jj < 6; ++jj) {
        int col = wc * 48 + jj * 8 + 2 * tk;
        float bx = __ldg(b1c + col), by = __ldg(b1c + col + 1);
        #pragma unroll
        for (int i = 0; i < 2; ++i) {
            int row = i * 16 + tg;
            __half2 h0 = __floats2half2_rn(mish_fast(c1[i][jj][0] + bx),
                                           mish_fast(c1[i][jj][1] + by));
            __half2 h1 = __floats2half2_rn(mish_fast(c1[i][jj][2] + bx),
                                           mish_fast(c1[i][jj][3] + by));
            *(__half2*)(Hh + row * H_STR + col) = h0;
            *(__half2*)(Hh + (row + 8) * H_STR + col) = h1;
        }
    }
    __syncthreads();   // H visible

    // ================= GEMM2: [32,384] @ W2 -> [32,256] =================
    float c2[2][4][4];
    #pragma unroll
    for (int i = 0; i < 2; ++i)
        #pragma unroll
        for (int jj = 0; jj < 4; ++jj)
            #pragma unroll
            for (int u = 0; u < 4; ++u) c2[i][jj][u] = 0.f;

    {
        const __half* Wb = g_W2h + ((wc * 32 + tg) << 5) + (tk << 3);
        uint4 bv[4], bn[4];
        #pragma unroll
        for (int jj = 0; jj < 4; ++jj)
            bv[jj] = *(const uint4*)(Wb + jj * 256);

        for (int ktp = 0; ktp < 12; ++ktp) {
            const int k0 = ktp << 5;
            uint32_t ae[2][4];
            #pragma unroll
            for (int i = 0; i < 2; ++i) {
                const __half* Hr = Hh + (i * 16 + tg) * H_STR + k0 + 2 * tk;
                ae[i][0] = *(const uint32_t*)(Hr);
                ae[i][1] = *(const uint32_t*)(Hr + 8 * H_STR);
                ae[i][2] = *(const uint32_t*)(Hr + 8);
                ae[i][3] = *(const uint32_t*)(Hr + 8 * H_STR + 8);
            }
            if (ktp + 1 < 12) {
                const __half* Wn = Wb + (ktp + 1) * 8192;
                #pragma unroll
                for (int jj = 0; jj < 4; ++jj)
                    bn[jj] = *(const uint4*)(Wn + jj * 256);
            }
            #pragma unroll
            for (int jj = 0; jj < 4; ++jj) {
                mma_f16(c2[0][jj], ae[0], bv[jj].x, bv[jj].y);
                mma_f16(c2[1][jj], ae[1], bv[jj].x, bv[jj].y);
            }
            uint32_t ao[2][4];
            #pragma unroll
            for (int i = 0; i < 2; ++i) {
                const __half* Hr = Hh + (i * 16 + tg) * H_STR + k0 + 16 + 2 * tk;
                ao[i][0] = *(const uint32_t*)(Hr);
                ao[i][1] = *(const uint32_t*)(Hr + 8 * H_STR);
                ao[i][2] = *(const uint32_t*)(Hr + 8);
                ao[i][3] = *(const uint32_t*)(Hr + 8 * H_STR + 8);
            }
            #pragma unroll
            for (int jj = 0; jj < 4; ++jj) {
                mma_f16(c2[0][jj], ao[0], bv[jj].z, bv[jj].w);
                mma_f16(c2[1][jj], ao[1], bv[jj].z, bv[jj].w);
            }
            #pragma unroll
            for (int jj = 0; jj < 4; ++jj) bv[jj] = bn[jj];
        }
    }

    // ---- output: +b2, mask, store ----
    #pragma unroll
    for (int jj = 0; jj < 4; ++jj) {
        int col = wc * 32 + jj * 8 + 2 * tk;
        float bx = __ldg(b2c + col), by = __ldg(b2c + col + 1);
        #pragma unroll
        for (int i = 0; i < 2; ++i) {
            int row = i * 16 + tg;
            float2 o0, o1;
            bool v0 = (r0 + row) < n, v1 = (r0 + row + 8) < n;
            o0.x = v0 ? c2[i][jj][0] + bx : 0.f;
            o0.y = v0 ? c2[i][jj][1] + by : 0.f;
            o1.x = v1 ? c2[i][jj][2] + bx : 0.f;
            o1.y = v1 ? c2[i][jj][3] + by : 0.f;
            *(float2*)(outb + (size_t)row * DIM_OUT + col) = o0;
            *(float2*)(outb + (size_t)(row + 8) * DIM_OUT + col) = o1;
        }
    }
}

// ===================== launch =====================
extern "C" void kernel_launch(void* const* d_in, const int* in_sizes, int n_in,
                              void* d_out, int out_size)
{
    const float* z     = (const float*)d_in[0];
    const float* sp_W1 = (const float*)d_in[1];
    const float* sp_b1 = (const float*)d_in[2];
    const float* sp_g  = (const float*)d_in[3];
    const float* sp_be = (const float*)d_in[4];
    const float* sp_W2 = (const float*)d_in[5];
    const float* sp_b2 = (const float*)d_in[6];
    const float* kn_W1 = (const float*)d_in[7];
    const float* kn_b1 = (const float*)d_in[8];
    const float* kn_g  = (const float*)d_in[9];
    const float* kn_be = (const float*)d_in[10];
    const float* kn_W2 = (const float*)d_in[11];
    const float* kn_b2 = (const float*)d_in[12];
    const float* de_W1 = (const float*)d_in[13];
    const float* de_b1 = (const float*)d_in[14];
    const float* de_W2 = (const float*)d_in[15];
    const float* de_b2 = (const float*)d_in[16];
    float* out = (float*)d_out;

    long long osz = (long long)out_size;
    int write_n    = (osz >= X_SIZE + B_DIM) ? 1 : 0;
    int write_mask = (osz >= X_SIZE + B_DIM + (long long)B_DIM * MAXN) ? 1 : 0;

    cudaFuncSetAttribute(decoder_kernel,
                         cudaFuncAttributeMaxDynamicSharedMemorySize,
                         DEC_SMEM_BYTES);

    sizepred_kernel<<<512, 256>>>(z, sp_W1, sp_b1, sp_g, sp_be, sp_W2, sp_b2,
                                  out, write_n, write_mask);
    keys_kernel<<<128, 512>>>(kn_W1, kn_b1, kn_g, kn_be, kn_W2, kn_b2);
    prep_kernel<<<1152, 256>>>(de_W1, de_W2);
    decoder_kernel<<<B_DIM * 4, 256, DEC_SMEM_BYTES>>>(z, de_b1, de_b2, out);
}

// round 12
// speedup vs baseline: 1.8691x; 1.0263x over previous
#include <cuda_runtime.h>
#include <cuda_fp16.h>
#include <math.h>
#include <cstdint>

#define B_DIM   2048
#define HID     512
#define DIM_OUT 256
#define MAXN    128
#define MID_S   256
#define MID_K   320
#define MID_D   384

#define X_SIZE  (2048LL*128*256)
#define N_OFF   X_SIZE
#define MASK_OFF (X_SIZE + 2048LL)

__device__ __align__(16) float g_keys[MAXN * HID];
__device__ int   g_n[B_DIM];
// W1^T fp16, k32 chunks, lane-group interleaved (see prep)
__device__ __align__(16) __half g_W1h[16 * 384 * 32];
__device__ __align__(16) __half g_W2h[12 * 256 * 32];

__device__ __forceinline__ float mishf(float x) {
    float sp = fmaxf(x, 0.f) + log1pf(expf(-fabsf(x)));
    return x * tanhf(sp);
}
__device__ __forceinline__ float mish_fast(float x) {
    float e = __expf(x);
    float y = 1.f + e;
    float d = fmaf(y, y, 1.f);
    return x - 2.f * x * __frcp_rn(d);
}
__device__ __forceinline__ void mma_f16(float* c, const uint32_t* a,
                                        uint32_t b0, uint32_t b1) {
    asm volatile(
        "mma.sync.aligned.m16n8k16.row.col.f32.f16.f16.f32 "
        "{%0,%1,%2,%3}, {%4,%5,%6,%7}, {%8,%9}, {%0,%1,%2,%3};"
        : "+f"(c[0]), "+f"(c[1]), "+f"(c[2]), "+f"(c[3])
        : "r"(a[0]), "r"(a[1]), "r"(a[2]), "r"(a[3]), "r"(b0), "r"(b1));
}
__device__ __forceinline__ void ldsm_x4(uint32_t* r, uint32_t addr) {
    asm volatile(
        "ldmatrix.sync.aligned.m8n8.x4.shared.b16 {%0,%1,%2,%3}, [%4];"
        : "=r"(r[0]), "=r"(r[1]), "=r"(r[2]), "=r"(r[3]) : "r"(addr));
}
__device__ __forceinline__ uint32_t smem_u32(const void* p) {
    uint32_t a;
    asm("{ .reg .u64 t; cvta.to.shared.u64 t, %1; cvt.u32.u64 %0, t; }" : "=r"(a) : "l"(p));
    return a;
}

// ===================== Kernel A: size_pred (8 rows/block, 256 blocks) ==========
__global__ __launch_bounds__(256)
void sizepred_kernel(const float* __restrict__ z,
                     const float* __restrict__ W1, const float* __restrict__ b1,
                     const float* __restrict__ g,  const float* __restrict__ be,
                     const float* __restrict__ W2, const float* __restrict__ b2,
                     float* __restrict__ out, int write_n, int write_mask)
{
    __shared__ float zsh[8][HID];
    __shared__ float hsh[8][MID_S];
    __shared__ float smean[8], srstd[8];
    __shared__ int   nsh[8];
    const int b0  = blockIdx.x * 8;
    const int tid = threadIdx.x;

    #pragma unroll
    for (int e = 0; e < 16; ++e) {
        int lin = e * 256 + tid;
        int bb = lin >> 9, i = lin & 511;
        zsh[bb][i] = z[(size_t)(b0 + bb) * HID + i];
    }
    __syncthreads();

    const int j = tid;
    float acc[8];
    {
        float bj = b1[j];
        #pragma unroll
        for (int bb = 0; bb < 8; ++bb) acc[bb] = bj;
    }
    for (int i = 0; i < HID; i += 8) {
        #pragma unroll
        for (int ii = 0; ii < 8; ++ii) {
            float w = W1[(size_t)(i + ii) * MID_S + j];
            #pragma unroll
            for (int bb = 0; bb < 8; ++bb)
                acc[bb] = fmaf(zsh[bb][i + ii], w, acc[bb]);
        }
    }
    #pragma unroll
    for (int bb = 0; bb < 8; ++bb) hsh[bb][j] = acc[bb];
    __syncthreads();

    const int wrow = tid >> 5, lane = tid & 31;
    {
        float s = 0.f, s2 = 0.f;
        for (int jj = lane; jj < MID_S; jj += 32) {
            float v = hsh[wrow][jj];
            s += v; s2 += v * v;
        }
        #pragma unroll
        for (int o = 16; o; o >>= 1) {
            s  += __shfl_xor_sync(0xffffffffu, s,  o);
            s2 += __shfl_xor_sync(0xffffffffu, s2, o);
        }
        if (lane == 0) {
            float m = s * (1.f / MID_S);
            float var = s2 * (1.f / MID_S) - m * m;
            smean[wrow] = m;
            srstd[wrow] = rsqrtf(var + 1e-5f);
        }
    }
    __syncthreads();

    {
        float gj = g[j], bej = be[j], w2j = W2[j];
        #pragma unroll
        for (int bb = 0; bb < 8; ++bb) {
            float v = (acc[bb] - smean[bb]) * srstd[bb] * gj + bej;
            hsh[bb][j] = mishf(v) * w2j;
        }
    }
    __syncthreads();

    {
        float s = 0.f;
        for (int jj = lane; jj < MID_S; jj += 32) s += hsh[wrow][jj];
        #pragma unroll
        for (int o = 16; o; o >>= 1) s += __shfl_xor_sync(0xffffffffu, s, o);
        if (lane == 0) {
            float logit = s + b2[0];
            float nf = fminf(fmaxf(rintf(logit), 0.f), (float)MAXN);
            int ni = (int)nf;
            g_n[b0 + wrow] = ni;
            nsh[wrow] = ni;
            if (write_n) out[N_OFF + b0 + wrow] = nf;
        }
    }
    __syncthreads();

    if (write_mask) {
        #pragma unroll
        for (int e = 0; e < 4; ++e) {
            int lin = e * 256 + tid;
            int bb = lin >> 7, kk = lin & 127;
            out[MASK_OFF + (size_t)(b0 + bb) * MAXN + kk] = (kk < nsh[bb]) ? 1.f : 0.f;
        }
    }
}

// ===================== Kernel B: keys =====================
__global__ __launch_bounds__(512)
void keys_kernel(const float* __restrict__ W1, const float* __restrict__ b1,
                 const float* __restrict__ g,  const float* __restrict__ be,
                 const float* __restrict__ W2, const float* __restrict__ b2)
{
    __shared__ float hs[MID_K];
    __shared__ float warp_s[16], warp_s2[16];
    __shared__ float st_mean, st_rstd;
    const int k = blockIdx.x;
    const int tid = threadIdx.x;
    const bool act = tid < MID_K;
    float v = 0.f;
    if (act) v = W1[(size_t)k * MID_K + tid] + b1[tid];
    float s = v, s2 = v * v;
    #pragma unroll
    for (int o = 16; o; o >>= 1) {
        s  += __shfl_xor_sync(0xffffffffu, s,  o);
        s2 += __shfl_xor_sync(0xffffffffu, s2, o);
    }
    const int wid = tid >> 5, lane = tid & 31;
    if (lane == 0) { warp_s[wid] = s; warp_s2[wid] = s2; }
    __syncthreads();
    if (wid == 0) {
        float ps  = (lane < 16) ? warp_s[lane]  : 0.f;
        float ps2 = (lane < 16) ? warp_s2[lane] : 0.f;
        #pragma unroll
        for (int o = 8; o; o >>= 1) {
            ps  += __shfl_xor_sync(0xffffffffu, ps,  o);
            ps2 += __shfl_xor_sync(0xffffffffu, ps2, o);
        }
        if (lane == 0) {
            float m = ps * (1.f / MID_K);
            float var = ps2 * (1.f / MID_K) - m * m;
            st_mean = m;
            st_rstd = rsqrtf(var + 1e-5f);
        }
    }
    __syncthreads();
    if (act) hs[tid] = mishf((v - st_mean) * st_rstd * g[tid] + be[tid]);
    __syncthreads();
    const int o = tid;
    float acc = b2[o];
    for (int jj = 0; jj < MID_K; jj += 4) {
        #pragma unroll
        for (int u = 0; u < 4; ++u)
            acc = fmaf(hs[jj + u], W2[(size_t)(jj + u) * HID + o], acc);
    }
    g_keys[(size_t)k * HID + o] = acc;
}

// ===================== Prep: fp16 interleaved transposed weights =====================
#define W1H_TOTAL (16 * 384 * 32)   // 196608
#define W2H_TOTAL (12 * 256 * 32)   // 98304
__global__ __launch_bounds__(256)
void prep_kernel(const float* __restrict__ W1, const float* __restrict__ W2)
{
    int id = blockIdx.x * 256 + threadIdx.x;
    if (id < W1H_TOTAL) {
        int ktp = id / 12288, rem = id % 12288;
        int nn = rem >> 5, h = rem & 31;
        int tk = h >> 3, pos = h & 7;
        int sub = pos & 3;
        int kl = ((pos >> 2) << 4) + ((sub < 2) ? (2 * tk + sub) : (2 * tk + 8 + sub - 2));
        g_W1h[id] = __float2half_rn(W1[(size_t)(ktp * 32 + kl) * MID_D + nn]);
    } else if (id < W1H_TOTAL + W2H_TOTAL) {
        int t = id - W1H_TOTAL;
        int ktp = t / 8192, rem = t % 8192;
        int nn = rem >> 5, h = rem & 31;
        int tk = h >> 3, pos = h & 7;
        int sub = pos & 3;
        int kl = ((pos >> 2) << 4) + ((sub < 2) ? (2 * tk + sub) : (2 * tk + 8 + sub - 2));
        g_W2h[t] = __float2half_rn(W2[(size_t)(ktp * 32 + kl) * DIM_OUT + nn]);
    }
}

// ===================== Kernel C: fp16 mma decoder + ldmatrix, 2 CTAs/SM ========
// A smem: [32 rows][520 halves]; rows 1040 B apart -> 260 words, 260%32=4 ->
// ldmatrix 8-row phases hit disjoint bank quads (conflict-free). H: [32][392].
#define A_STR 520
#define H_STR 392
#define ZS_BYTE_OFF 33280                    // 32*520*2
#define DEC_SMEM_BYTES (ZS_BYTE_OFF + 2048)  // 35328

__global__ __launch_bounds__(256, 2)
void decoder_kernel(const float* __restrict__ z,
                    const float* __restrict__ b1c,
                    const float* __restrict__ b2c,
                    float* __restrict__ out)
{
    extern __shared__ char smraw[];
    __half* Ah = (__half*)smraw;
    __half* Hh = (__half*)smraw;
    float*  zs = (float*)(smraw + ZS_BYTE_OFF);

    const int b    = blockIdx.x >> 2;
    const int r0   = (blockIdx.x & 3) * 32;
    const int tid  = threadIdx.x;
    const int wc   = tid >> 5;          // 0..7 warp col
    const int lane = tid & 31;
    const int tg   = lane >> 2;         // 0..7
    const int tk   = lane & 3;          // 0..3

    const int n = g_n[b];
    float* outb = out + (size_t)b * MAXN * DIM_OUT + (size_t)r0 * DIM_OUT;

    if (r0 >= n) {
        float4 zz = make_float4(0.f, 0.f, 0.f, 0.f);
        float4* o4 = (float4*)outb;
        #pragma unroll
        for (int e = 0; e < 8; ++e) o4[e * 256 + tid] = zz;
        return;
    }

    zs[tid] = z[(size_t)b * HID + tid];
    zs[256 + tid] = z[(size_t)b * HID + 256 + tid];
    __syncthreads();

    const float4* K4 = (const float4*)g_keys;
    const float4* Z4 = (const float4*)zs;

    // ---- build A (fp16): A[r][k] = half(keys[r0+r][k] * z[k]) ----
    #pragma unroll
    for (int e = 0; e < 16; ++e) {
        int idx = e * 256 + tid;        // 0..4095
        int r = idx >> 7, q = idx & 127;
        float4 kv = K4[(size_t)(r0 + r) * 128 + q];
        float4 zv = Z4[q];
        __half2 h0 = __floats2half2_rn(kv.x * zv.x, kv.y * zv.y);
        __half2 h1 = __floats2half2_rn(kv.z * zv.z, kv.w * zv.w);
        uint2 pk;
        pk.x = *(uint32_t*)&h0;
        pk.y = *(uint32_t*)&h1;
        *(uint2*)(Ah + r * A_STR + q * 4) = pk;
    }
    __syncthreads();   // A visible

    // ldmatrix lane addressing: lanes 0-15 -> rows 0-15 col k0;
    // lanes 16-31 -> rows 0-15 col k0+8
    const int rowl = lane & 15;
    const int colg = (lane >> 4) << 3;
    const uint32_t smbA = smem_u32(Ah);
    const uint32_t aAddr0 = smbA + (uint32_t)(rowl * A_STR + colg) * 2;
    const uint32_t aAddr1 = smbA + (uint32_t)((16 + rowl) * A_STR + colg) * 2;
    const uint32_t hAddr0 = smbA + (uint32_t)(rowl * H_STR + colg) * 2;
    const uint32_t hAddr1 = smbA + (uint32_t)((16 + rowl) * H_STR + colg) * 2;

    // ================= GEMM1: [32,512] @ W1 -> [32,384] =================
    float c1[2][6][4];
    #pragma unroll
    for (int i = 0; i < 2; ++i)
        #pragma unroll
        for (int jj = 0; jj < 6; ++jj)
            #pragma unroll
            for (int u = 0; u < 4; ++u) c1[i][jj][u] = 0.f;

    {
        const __half* Wb = g_W1h + ((wc * 48 + tg) << 5) + (tk << 3);
        uint4 bv[6], bn[6];
        #pragma unroll
        for (int jj = 0; jj < 6; ++jj)
            bv[jj] = *(const uint4*)(Wb + jj * 256);

        for (int ktp = 0; ktp < 16; ++ktp) {
            const uint32_t kb = (uint32_t)(ktp << 6);   // k0*2 bytes
            uint32_t ae[2][4], ao[2][4];
            ldsm_x4(ae[0], aAddr0 + kb);
            ldsm_x4(ae[1], aAddr1 + kb);
            if (ktp + 1 < 16) {
                const __half* Wn = Wb + (ktp + 1) * 12288;
                #pragma unroll
                for (int jj = 0; jj < 6; ++jj)
                    bn[jj] = *(const uint4*)(Wn + jj * 256);
            }
            #pragma unroll
            for (int jj = 0; jj < 6; ++jj) {
                mma_f16(c1[0][jj], ae[0], bv[jj].x, bv[jj].y);
                mma_f16(c1[1][jj], ae[1], bv[jj].x, bv[jj].y);
            }
            ldsm_x4(ao[0], aAddr0 + kb + 32);
            ldsm_x4(ao[1], aAddr1 + kb + 32);
            #pragma unroll
            for (int jj = 0; jj < 6; ++jj) {
                mma_f16(c1[0][jj], ao[0], bv[jj].z, bv[jj].w);
                mma_f16(c1[1][jj], ao[1], bv[jj].z, bv[jj].w);
            }
            #pragma unroll
            for (int jj = 0; jj < 6; ++jj) bv[jj] = bn[jj];
        }
    }
    __syncthreads();   // all A reads done -> region becomes H

    // ---- epilogue 1: +b1, mish, fp16, store H ----
    #pragma unroll
    for (int jj = 0; jj < 6; ++jj) {
        int col = wc * 48 + jj * 8 + 2 * tk;
        float bx = __ldg(b1c + col), by = __ldg(b1c + col + 1);
        #pragma unroll
        for (int i = 0; i < 2; ++i) {
            int row = i * 16 + tg;
            __half2 h0 = __floats2half2_rn(mish_fast(c1[i][jj][0] + bx),
                                           mish_fast(c1[i][jj][1] + by));
            __half2 h1 = __floats2half2_rn(mish_fast(c1[i][jj][2] + bx),
                                           mish_fast(c1[i][jj][3] + by));
            *(__half2*)(Hh + row * H_STR + col) = h0;
            *(__half2*)(Hh + (row + 8) * H_STR + col) = h1;
        }
    }
    __syncthreads();   // H visible

    // ================= GEMM2: [32,384] @ W2 -> [32,256] =================
    float c2[2][4][4];
    #pragma unroll
    for (int i = 0; i < 2; ++i)
        #pragma unroll
        for (int jj = 0; jj < 4; ++jj)
            #pragma unroll
            for (int u = 0; u < 4; ++u) c2[i][jj][u] = 0.f;

    {
        const __half* Wb = g_W2h + ((wc * 32 + tg) << 5) + (tk << 3);
        uint4 bv[4], bn[4];
        #pragma unroll
        for (int jj = 0; jj < 4; ++jj)
            bv[jj] = *(const uint4*)(Wb + jj * 256);

        for (int ktp = 0; ktp < 12; ++ktp) {
            const uint32_t kb = (uint32_t)(ktp << 6);
            uint32_t ae[2][4], ao[2][4];
            ldsm_x4(ae[0], hAddr0 + kb);
            ldsm_x4(ae[1], hAddr1 + kb);
            if (ktp + 1 < 12) {
                const __half* Wn = Wb + (ktp + 1) * 8192;
                #pragma unroll
                for (int jj = 0; jj < 4; ++jj)
                    bn[jj] = *(const uint4*)(Wn + jj * 256);
            }
            #pragma unroll
            for (int jj = 0; jj < 4; ++jj) {
                mma_f16(c2[0][jj], ae[0], bv[jj].x, bv[jj].y);
                mma_f16(c2[1][jj], ae[1], bv[jj].x, bv[jj].y);
            }
            ldsm_x4(ao[0], hAddr0 + kb + 32);
            ldsm_x4(ao[1], hAddr1 + kb + 32);
            #pragma unroll
            for (int jj = 0; jj < 4; ++jj) {
                mma_f16(c2[0][jj], ao[0], bv[jj].z, bv[jj].w);
                mma_f16(c2[1][jj], ao[1], bv[jj].z, bv[jj].w);
            }
            #pragma unroll
            for (int jj = 0; jj < 4; ++jj) bv[jj] = bn[jj];
        }
    }

    // ---- output: +b2, mask, store ----
    #pragma unroll
    for (int jj = 0; jj < 4; ++jj) {
        int col = wc * 32 + jj * 8 + 2 * tk;
        float bx = __ldg(b2c + col), by = __ldg(b2c + col + 1);
        #pragma unroll
        for (int i = 0; i < 2; ++i) {
            int row = i * 16 + tg;
            float2 o0, o1;
            bool v0 = (r0 + row) < n, v1 = (r0 + row + 8) < n;
            o0.x = v0 ? c2[i][jj][0] + bx : 0.f;
            o0.y = v0 ? c2[i][jj][1] + by : 0.f;
            o1.x = v1 ? c2[i][jj][2] + bx : 0.f;
            o1.y = v1 ? c2[i][jj][3] + by : 0.f;
            *(float2*)(outb + (size_t)row * DIM_OUT + col) = o0;
            *(float2*)(outb + (size_t)(row + 8) * DIM_OUT + col) = o1;
        }
    }
}

// ===================== launch =====================
extern "C" void kernel_launch(void* const* d_in, const int* in_sizes, int n_in,
                              void* d_out, int out_size)
{
    const float* z     = (const float*)d_in[0];
    const float* sp_W1 = (const float*)d_in[1];
    const float* sp_b1 = (const float*)d_in[2];
    const float* sp_g  = (const float*)d_in[3];
    const float* sp_be = (const float*)d_in[4];
    const float* sp_W2 = (const float*)d_in[5];
    const float* sp_b2 = (const float*)d_in[6];
    const float* kn_W1 = (const float*)d_in[7];
    const float* kn_b1 = (const float*)d_in[8];
    const float* kn_g  = (const float*)d_in[9];
    const float* kn_be = (const float*)d_in[10];
    const float* kn_W2 = (const float*)d_in[11];
    const float* kn_b2 = (const float*)d_in[12];
    const float* de_W1 = (const float*)d_in[13];
    const float* de_b1 = (const float*)d_in[14];
    const float* de_W2 = (const float*)d_in[15];
    const float* de_b2 = (const float*)d_in[16];
    float* out = (float*)d_out;

    long long osz = (long long)out_size;
    int write_n    = (osz >= X_SIZE + B_DIM) ? 1 : 0;
    int write_mask = (osz >= X_SIZE + B_DIM + (long long)B_DIM * MAXN) ? 1 : 0;

    cudaFuncSetAttribute(decoder_kernel,
                         cudaFuncAttributeMaxDynamicSharedMemorySize,
                         DEC_SMEM_BYTES);

    sizepred_kernel<<<256, 256>>>(z, sp_W1, sp_b1, sp_g, sp_be, sp_W2, sp_b2,
                                  out, write_n, write_mask);
    keys_kernel<<<128, 512>>>(kn_W1, kn_b1, kn_g, kn_be, kn_W2, kn_b2);
    prep_kernel<<<1152, 256>>>(de_W1, de_W2);
    decoder_kernel<<<B_DIM * 4, 256, DEC_SMEM_BYTES>>>(z, de_b1, de_b2, out);
}